// round 14
// baseline (speedup 1.0000x reference)
#include <cuda_runtime.h>
#include <cuda_fp16.h>
#include <cstdint>

// ---------------------------------------------------------------------------
// S4D kernel materialization via raw mma.sync (HMMA.16816), sm_100-safe.
//   K[d,l] = 2*Re( sum_n Cc[d,n] * exp(dtA[d,n] * l) ),  D=512, N=32, L=8192
//
// Split l = 64*m + b:  K[d,64m+b] = sum_k A[m,k]*B[b,k]  (real GEMM, K=64)
//   A[m, n] = Re(u), A[m,32+n] = Im(u),  u = 2*Cc_n * exp(dtA_n*64m)
//   B[b, n] = Re(w), B[b,32+n] = -Im(w), w = exp(dtA_n*b)
//
// Round 13 (re-bench; previous attempt hit an infra failure) = Round 12 +
// coalesced epilogue: MMA accumulators are staged in shared memory (STS.64,
// ~2-way worst case) and written out with fully coalesced LDS.128+STG.128
// (4 wavefronts per store inst instead of 8 per STG.64). R12 analysis:
// scattered stores were ~7.1k L1 cycles/SM = 41% of the wall.
// ---------------------------------------------------------------------------

#define D_MODEL 512
#define SEQ     8192
#define NST     32
#define TROW    34                    // float2 per table row (pad)
#define BROW32  36                    // u32 per B row (72 halves = 144 B)
#define SROW    68                    // floats per stage row (64 + 4 pad)

// ---- helpers ---------------------------------------------------------------
__device__ __forceinline__ float2 cmul(float2 a, float2 b) {
    return make_float2(a.x * b.x - a.y * b.y, a.x * b.y + a.y * b.x);
}
// exp(scale*(dtAr + i*dtAi)), fp32 Cody-Waite mod-2pi (validated R7/R11).
__device__ __forceinline__ float2 cexp_fast(float dtAr, float dtAi, float scale) {
    float e  = __expf(scale * dtAr);
    float mi = scale * dtAi;
    float k  = rintf(mi * 0.15915494f);
    float th = fmaf(-k, 6.2831855f, mi);
    th = fmaf(k, 1.7484556e-7f, th);
    float s, c;
    __sincosf(th, &s, &c);
    return make_float2(e * c, e * s);
}
// pack two fp32 -> half2 (v0 in low half)
__device__ __forceinline__ uint32_t pkh2(float v0, float v1) {
    __half2 h = __halves2half2(__float2half_rn(v0), __float2half_rn(v1));
    return *(uint32_t*)&h;
}
__device__ __forceinline__ void mma16816(float* acc, const uint32_t* a,
                                         const uint32_t* b) {
    asm volatile(
        "mma.sync.aligned.m16n8k16.row.col.f32.f16.f16.f32 "
        "{%0,%1,%2,%3}, {%4,%5,%6,%7}, {%8,%9}, {%0,%1,%2,%3};"
        : "+f"(acc[0]), "+f"(acc[1]), "+f"(acc[2]), "+f"(acc[3])
        : "r"(a[0]), "r"(a[1]), "r"(a[2]), "r"(a[3]), "r"(b[0]), "r"(b[1]));
}

// ---------------------------------------------------------------------------
__global__ void __launch_bounds__(128, 4)
s4d_mma_kernel(const float* __restrict__ log_dt,
               const float* __restrict__ log_A_real,
               const float* __restrict__ A_imag,
               const float2* __restrict__ C,
               float* __restrict__ out)
{
    __shared__ float2   tR[16 * TROW];        // rows 0-7: r^i ; 8-15: r^(8j)
    __shared__ uint32_t Bs[64 * BROW32];      // B fp16 [b][72 halves]
    __shared__ float    stage[128 * SROW];    // D staging, 64 cols + 4 pad

    const int d   = blockIdx.x;
    const int tid = threadIdx.x;
    const int w   = tid >> 5;
    const int l   = tid & 31;
    const int q   = l & 3;
    const int g   = l >> 2;

    // ---- per-lane-n constants (lane l owns state n = l) --------------------
    int i = d * NST + l;
    float dt   = __expf(log_dt[d]);
    float Ar   = -__expf(log_A_real[i]);
    float Ai   = A_imag[i];
    float dtAr = Ar * dt;
    float dtAi = Ai * dt;

    // discretized C with final 2x folded in (fast intrinsics; |dtAi|<=0.314)
    float er = __expf(dtAr);
    float sn, cs;
    __sincosf(dtAi, &sn, &cs);
    float Er = er * cs - 1.0f, Ei = er * sn;
    float ar8 = Ar + 1e-8f;
    float inv = 1.0f / (ar8 * ar8 + Ai * Ai);
    float qr = (Er * ar8 + Ei * Ai) * inv;
    float qi = (Ei * ar8 - Er * Ai) * inv;
    float2 Cv = C[i];
    float Ccr = 2.0f * (Cv.x * qr - Cv.y * qi);
    float Cci = 2.0f * (Cv.x * qi + Cv.y * qr);
    float2 r512 = cexp_fast(dtAr, dtAi, 512.0f);

    // ---- Phase 1: tR tables (16 rows; warp w builds rows 4w..4w+3) ---------
#pragma unroll
    for (int rr = 0; rr < 4; rr++) {
        int row = 4 * w + rr;
        float scale = (row < 8) ? (float)row : (float)(8 * (row - 8));
        tR[row * TROW + l] = cexp_fast(dtAr, dtAi, scale);
    }
    __syncthreads();

    // ---- Phase 2: B in smem (b = tid>>1, 8 n2-units each) ------------------
    {
        int b  = tid >> 1;
        int h0 = (tid & 1) * 8;
        const float4* sa = (const float4*)(tR + (b & 7) * TROW);
        const float4* sb = (const float4*)(tR + (8 + (b >> 3)) * TROW);
#pragma unroll
        for (int n2i = 0; n2i < 8; n2i++) {
            int n2 = h0 + n2i;
            float4 a = sa[n2], p = sb[n2];
            float2 w0 = cmul(make_float2(a.x, a.y), make_float2(p.x, p.y));
            float2 w1 = cmul(make_float2(a.z, a.w), make_float2(p.z, p.w));
            Bs[b * BROW32 + n2]      = pkh2(w0.x, w1.x);    // Re  (k = 2n2,2n2+1)
            Bs[b * BROW32 + 16 + n2] = pkh2(-w0.y, -w1.y);  // -Im (k = 32+2n2,..)
        }
    }

    // ---- Phase 3 (overlapped with B wait): A fragments in registers --------
    uint32_t Afr[2][4][4];                   // [mtile][kstep][reg]
    const int m1 = 32 * w + g;
    const float fm = (float)(64 * m1);
#pragma unroll
    for (int p = 0; p < 4; p++) {
        int n0 = 2 * q + 8 * (p & 1) + 16 * (p >> 1);
        float uRe[2][4], uIm[2][4];
#pragma unroll
        for (int e = 0; e < 2; e++) {
            int nn = n0 + e;
            float dar = __shfl_sync(0xffffffffu, dtAr, nn);
            float dai = __shfl_sync(0xffffffffu, dtAi, nn);
            float ccr = __shfl_sync(0xffffffffu, Ccr, nn);
            float cci = __shfl_sync(0xffffffffu, Cci, nn);
            float r5r = __shfl_sync(0xffffffffu, r512.x, nn);
            float r5i = __shfl_sync(0xffffffffu, r512.y, nn);
            float2 x  = cexp_fast(dar, dai, fm);            // r^(64*m1)
            float2 u1 = cmul(make_float2(ccr, cci), x);     // m1
            float2 r5 = make_float2(r5r, r5i);
            float2 u2 = cmul(u1, r5);                       // m1+8
            float2 u3 = cmul(u2, r5);                       // m1+16
            float2 u4 = cmul(u3, r5);                       // m1+24
            uRe[e][0] = u1.x; uIm[e][0] = u1.y;
            uRe[e][1] = u2.x; uIm[e][1] = u2.y;
            uRe[e][2] = u3.x; uIm[e][2] = u3.y;
            uRe[e][3] = u4.x; uIm[e][3] = u4.y;
        }
        int s_re = p >> 1;          // kstep for Re (s=0,1); Im at s_re+2
        int ab   = 2 * (p & 1);     // reg pair offset
        Afr[0][s_re][ab + 0]     = pkh2(uRe[0][0], uRe[1][0]);
        Afr[0][s_re][ab + 1]     = pkh2(uRe[0][1], uRe[1][1]);
        Afr[1][s_re][ab + 0]     = pkh2(uRe[0][2], uRe[1][2]);
        Afr[1][s_re][ab + 1]     = pkh2(uRe[0][3], uRe[1][3]);
        Afr[0][s_re + 2][ab + 0] = pkh2(uIm[0][0], uIm[1][0]);
        Afr[0][s_re + 2][ab + 1] = pkh2(uIm[0][1], uIm[1][1]);
        Afr[1][s_re + 2][ab + 0] = pkh2(uIm[0][2], uIm[1][2]);
        Afr[1][s_re + 2][ab + 1] = pkh2(uIm[0][3], uIm[1][3]);
    }
    __syncthreads();                 // B ready

    // ---- Phase 4: MMA, accumulators staged to smem -------------------------
    // stage[row][col]: row = 32w + 16mt + g (+8), col = 8bt + 2q.
#pragma unroll
    for (int bt = 0; bt < 8; bt++) {
        uint32_t Bfr[4][2];
#pragma unroll
        for (int s = 0; s < 4; s++) {
            const uint32_t* brow = Bs + (8 * bt + g) * BROW32 + 8 * s + q;
            Bfr[s][0] = brow[0];
            Bfr[s][1] = brow[4];
        }
#pragma unroll
        for (int mt = 0; mt < 2; mt++) {
            float acc[4] = {0.f, 0.f, 0.f, 0.f};
#pragma unroll
            for (int s = 0; s < 4; s++) mma16816(acc, Afr[mt][s], Bfr[s]);
            int r0 = (32 * w + 16 * mt + g) * SROW + 8 * bt + 2 * q;
            *(float2*)(stage + r0)            = make_float2(acc[0], acc[1]);
            *(float2*)(stage + r0 + 8 * SROW) = make_float2(acc[2], acc[3]);
        }
    }
    __syncthreads();                 // stage complete

    // ---- Phase 5: coalesced copy-out (thread: 16 x float4, contiguous) -----
    float* dst = out + (size_t)d * SEQ;
#pragma unroll
    for (int rnd = 0; rnd < 16; rnd++) {
        int L = rnd * 512 + tid * 4;
        int row = L >> 6;
        int col = L & 63;
        float4 v = *(const float4*)(stage + row * SROW + col);
        *(float4*)(dst + L) = v;
    }
}

// ---------------------------------------------------------------------------
extern "C" void kernel_launch(void* const* d_in, const int* in_sizes, int n_in,
                              void* d_out, int out_size)
{
    const float*  log_dt     = (const float*)d_in[0];
    const float*  log_A_real = (const float*)d_in[1];
    const float*  A_imag     = (const float*)d_in[2];
    const float2* C          = (const float2*)d_in[3];
    float* out = (float*)d_out;

    s4d_mma_kernel<<<D_MODEL, 128>>>(log_dt, log_A_real, A_imag, C, out);
}